// round 5
// baseline (speedup 1.0000x reference)
#include <cuda_runtime.h>
#include <cstdint>

#define BB 16
#define CC 64
#define NPIX 65536          // 256*256
#define NBVEC 4
#define INV_TEMP (1.0f/20.0f)
#define PIN_BATCHES 6       // 6 * 16MB = 96MB of x kept L2-resident

// ---------------- device scratch (no allocations allowed) ----------------
__device__ float g_raw[BB][CC];
__device__ float g_vec[BB][CC];
__device__ float g_simsum[BB];
__device__ unsigned long long g_amax[BB];
__device__ float g_score[BB * NPIX];

// ---------------- helpers ----------------
__device__ __forceinline__ unsigned long long pack_score(float s, int n) {
    // score >= 0 -> float bits order-preserving; invert idx so ties pick lowest n.
    return ((unsigned long long)__float_as_uint(s) << 32) |
           (unsigned long long)(0xFFFFFFFFu - (unsigned)n);
}

// 256-bit loads: the ONLY widths sm_103a ptxas allows L2:: policies on.
__device__ __forceinline__ void ldg8_pin(const float* p, float4& a, float4& b) {
    unsigned r0, r1, r2, r3, r4, r5, r6, r7;
    asm volatile("ld.global.nc.L2::evict_last.v8.b32 {%0,%1,%2,%3,%4,%5,%6,%7}, [%8];"
                 : "=r"(r0), "=r"(r1), "=r"(r2), "=r"(r3),
                   "=r"(r4), "=r"(r5), "=r"(r6), "=r"(r7) : "l"(p));
    a.x = __uint_as_float(r0); a.y = __uint_as_float(r1);
    a.z = __uint_as_float(r2); a.w = __uint_as_float(r3);
    b.x = __uint_as_float(r4); b.y = __uint_as_float(r5);
    b.z = __uint_as_float(r6); b.w = __uint_as_float(r7);
}
__device__ __forceinline__ void ldg8(const float* p, float4& a, float4& b) {
    unsigned r0, r1, r2, r3, r4, r5, r6, r7;
    asm volatile("ld.global.nc.v8.b32 {%0,%1,%2,%3,%4,%5,%6,%7}, [%8];"
                 : "=r"(r0), "=r"(r1), "=r"(r2), "=r"(r3),
                   "=r"(r4), "=r"(r5), "=r"(r6), "=r"(r7) : "l"(p));
    a.x = __uint_as_float(r0); a.y = __uint_as_float(r1);
    a.z = __uint_as_float(r2); a.w = __uint_as_float(r3);
    b.x = __uint_as_float(r4); b.y = __uint_as_float(r5);
    b.z = __uint_as_float(r6); b.w = __uint_as_float(r7);
}

// ---------------- kernel 1: zero selectedPos + reset amax ----------------
__global__ void zero_kernel(float* __restrict__ selPos) {
    int i = blockIdx.x * blockDim.x + threadIdx.x;
    selPos[i] = 0.0f;
    if (blockIdx.x == 0 && threadIdx.x < BB) g_amax[threadIdx.x] = 0ull;
}

// ---------------- kernel 2: argmax of score_init per batch ----------------
__global__ void argmax0_kernel(const float* __restrict__ score) {
    int b = blockIdx.y;
    const float* s = score + (size_t)b * NPIX;
    unsigned long long m = 0ull;
    for (int n = blockIdx.x * blockDim.x + threadIdx.x; n < NPIX;
         n += gridDim.x * blockDim.x) {
        unsigned long long p = pack_score(s[n], n);
        m = (p > m) ? p : m;
    }
    #pragma unroll
    for (int o = 16; o; o >>= 1) {
        unsigned long long t = __shfl_down_sync(0xFFFFFFFFu, m, o);
        m = (t > m) ? t : m;
    }
    __shared__ unsigned long long sm[8];
    int w = threadIdx.x >> 5;
    if ((threadIdx.x & 31) == 0) sm[w] = m;
    __syncthreads();
    if (threadIdx.x == 0) {
        unsigned long long mm = sm[0];
        for (int i = 1; i < (int)(blockDim.x >> 5); i++)
            mm = (sm[i] > mm) ? sm[i] : mm;
        atomicMax(&g_amax[b], mm);
    }
}

// -------- kernel 3: finish previous iter + prep next ----------------------
__global__ void between_kernel(const float* __restrict__ x,
                               float* __restrict__ vecList,
                               int finish_iter, int do_prep) {
    int b = blockIdx.x, c = threadIdx.x;   // 64 threads
    float fin = 0.0f;
    unsigned ind = 0;
    if (finish_iter >= 0)
        fin = g_vec[b][c] / g_simsum[b];
    if (do_prep)
        ind = 0xFFFFFFFFu - (unsigned)(g_amax[b] & 0xFFFFFFFFull);
    __syncthreads();
    if (finish_iter >= 0)
        vecList[((size_t)b * NBVEC + finish_iter) * CC + c] = fin;
    if (do_prep) {
        g_raw[b][c] = x[((size_t)(b * CC + c)) * NPIX + ind];
        g_vec[b][c] = 0.0f;
        if (c == 0) { g_simsum[b] = 0.0f; g_amax[b] = 0ull; }
    }
}

// ---------------- kernel 4: fused main pass ----------------
// In-warp split: lane l -> cg = l>>2 (8 channel-groups of 8 ch), q = l&3
// (4 pixel-octets of 8 px). Warp covers 32 px/tile; block 256 px/tile.
// Cross-cg d2 reduce = 3x shfl_xor. NO block barriers in the main loop.
// Batches [0,PIN_BATCHES) use L2::evict_last 256-bit loads (uniform per block).
__global__ void __launch_bounds__(256, 2)
main_kernel(const float* __restrict__ x,
            const float* __restrict__ score_init,
            int first_iter,
            float* __restrict__ simList,
            int iter) {
    const int b = blockIdx.y;
    const int t = threadIdx.x;
    const int w = t >> 5;
    const int l = t & 31;
    const int cg = l >> 2;          // 0..7  -> channels cg*8 .. cg*8+7
    const int q  = l & 3;           // 0..3  -> pixel octet
    const bool pin = (b < PIN_BATCHES);

    const float* xb   = x + (size_t)b * CC * NPIX + (size_t)cg * 8 * NPIX;
    const float* scin = (first_iter ? score_init : (const float*)g_score) + (size_t)b * NPIX;
    float* scout = g_score + (size_t)b * NPIX;
    float* simo  = simList + ((size_t)b * NBVEC + iter) * NPIX;

    __shared__ float sraw_sh[CC];
    if (t < CC) sraw_sh[t] = g_raw[b][t];
    __syncthreads();
    float sraw[8];
    #pragma unroll
    for (int i = 0; i < 8; i++) sraw[i] = sraw_sh[cg * 8 + i];

    float acc[8];
    #pragma unroll
    for (int i = 0; i < 8; i++) acc[i] = 0.0f;
    float lsum = 0.0f;
    unsigned long long lmax = 0ull;

    for (int tile = blockIdx.x; tile < NPIX / 256; tile += gridDim.x) {
        const int n0 = tile * 256 + w * 32 + q * 8;   // 32B-aligned

        float4 va[8], vb[8];                          // 8 channels x 8 pixels
        if (pin) {
            #pragma unroll
            for (int i = 0; i < 8; i++)
                ldg8_pin(xb + (size_t)i * NPIX + n0, va[i], vb[i]);
        } else {
            #pragma unroll
            for (int i = 0; i < 8; i++)
                ldg8(xb + (size_t)i * NPIX + n0, va[i], vb[i]);
        }

        float4 d2a = make_float4(0.f, 0.f, 0.f, 0.f);
        float4 d2b = make_float4(0.f, 0.f, 0.f, 0.f);
        #pragma unroll
        for (int i = 0; i < 8; i++) {
            float r = sraw[i], d;
            d = va[i].x - r; d2a.x = fmaf(d, d, d2a.x);
            d = va[i].y - r; d2a.y = fmaf(d, d, d2a.y);
            d = va[i].z - r; d2a.z = fmaf(d, d, d2a.z);
            d = va[i].w - r; d2a.w = fmaf(d, d, d2a.w);
            d = vb[i].x - r; d2b.x = fmaf(d, d, d2b.x);
            d = vb[i].y - r; d2b.y = fmaf(d, d, d2b.y);
            d = vb[i].z - r; d2b.z = fmaf(d, d, d2b.z);
            d = vb[i].w - r; d2b.w = fmaf(d, d, d2b.w);
        }
        // cross-cg butterfly (cg lives in lane bits 2..4)
        #pragma unroll
        for (int m = 4; m <= 16; m <<= 1) {
            d2a.x += __shfl_xor_sync(0xFFFFFFFFu, d2a.x, m);
            d2a.y += __shfl_xor_sync(0xFFFFFFFFu, d2a.y, m);
            d2a.z += __shfl_xor_sync(0xFFFFFFFFu, d2a.z, m);
            d2a.w += __shfl_xor_sync(0xFFFFFFFFu, d2a.w, m);
            d2b.x += __shfl_xor_sync(0xFFFFFFFFu, d2b.x, m);
            d2b.y += __shfl_xor_sync(0xFFFFFFFFu, d2b.y, m);
            d2b.z += __shfl_xor_sync(0xFFFFFFFFu, d2b.z, m);
            d2b.w += __shfl_xor_sync(0xFFFFFFFFu, d2b.w, m);
        }

        float4 sa, sb;
        sa.x = expf(-sqrtf(fmaxf(d2a.x, 1e-12f)) * INV_TEMP);
        sa.y = expf(-sqrtf(fmaxf(d2a.y, 1e-12f)) * INV_TEMP);
        sa.z = expf(-sqrtf(fmaxf(d2a.z, 1e-12f)) * INV_TEMP);
        sa.w = expf(-sqrtf(fmaxf(d2a.w, 1e-12f)) * INV_TEMP);
        sb.x = expf(-sqrtf(fmaxf(d2b.x, 1e-12f)) * INV_TEMP);
        sb.y = expf(-sqrtf(fmaxf(d2b.y, 1e-12f)) * INV_TEMP);
        sb.z = expf(-sqrtf(fmaxf(d2b.z, 1e-12f)) * INV_TEMP);
        sb.w = expf(-sqrtf(fmaxf(d2b.w, 1e-12f)) * INV_TEMP);

        #pragma unroll
        for (int i = 0; i < 8; i++) {
            acc[i] = fmaf(va[i].x, sa.x, acc[i]);
            acc[i] = fmaf(va[i].y, sa.y, acc[i]);
            acc[i] = fmaf(va[i].z, sa.z, acc[i]);
            acc[i] = fmaf(va[i].w, sa.w, acc[i]);
            acc[i] = fmaf(vb[i].x, sb.x, acc[i]);
            acc[i] = fmaf(vb[i].y, sb.y, acc[i]);
            acc[i] = fmaf(vb[i].z, sb.z, acc[i]);
            acc[i] = fmaf(vb[i].w, sb.w, acc[i]);
        }

        if (cg == 0) {
            *(float4*)(simo + n0)     = sa;
            *(float4*)(simo + n0 + 4) = sb;
            lsum += ((sa.x + sa.y) + (sa.z + sa.w)) +
                    ((sb.x + sb.y) + (sb.z + sb.w));
        } else if (cg == 1) {
            float4 ca = *(const float4*)(scin + n0);
            float4 cb = *(const float4*)(scin + n0 + 4);
            float4 na, nb;
            na.x = (1.0f - sa.x) * ca.x;  na.y = (1.0f - sa.y) * ca.y;
            na.z = (1.0f - sa.z) * ca.z;  na.w = (1.0f - sa.w) * ca.w;
            nb.x = (1.0f - sb.x) * cb.x;  nb.y = (1.0f - sb.y) * cb.y;
            nb.z = (1.0f - sb.z) * cb.z;  nb.w = (1.0f - sb.w) * cb.w;
            *(float4*)(scout + n0)     = na;
            *(float4*)(scout + n0 + 4) = nb;
            unsigned long long p;
            p = pack_score(na.x, n0 + 0); lmax = (p > lmax) ? p : lmax;
            p = pack_score(na.y, n0 + 1); lmax = (p > lmax) ? p : lmax;
            p = pack_score(na.z, n0 + 2); lmax = (p > lmax) ? p : lmax;
            p = pack_score(na.w, n0 + 3); lmax = (p > lmax) ? p : lmax;
            p = pack_score(nb.x, n0 + 4); lmax = (p > lmax) ? p : lmax;
            p = pack_score(nb.y, n0 + 5); lmax = (p > lmax) ? p : lmax;
            p = pack_score(nb.z, n0 + 6); lmax = (p > lmax) ? p : lmax;
            p = pack_score(nb.w, n0 + 7); lmax = (p > lmax) ? p : lmax;
        }
    }

    // ---- final reductions (once per kernel) ----
    // acc[i]: sum over the 4 q-lanes within each cg group (xor 1,2 stay in-group)
    #pragma unroll
    for (int i = 0; i < 8; i++) {
        float a = acc[i];
        a += __shfl_xor_sync(0xFFFFFFFFu, a, 1);
        a += __shfl_xor_sync(0xFFFFFFFFu, a, 2);
        if (q == 0) atomicAdd(&g_vec[b][cg * 8 + i], a);
    }
    lsum += __shfl_xor_sync(0xFFFFFFFFu, lsum, 1);
    lsum += __shfl_xor_sync(0xFFFFFFFFu, lsum, 2);
    if (l == 0) atomicAdd(&g_simsum[b], lsum);       // cg==0 lanes are l=0..3
    {
        unsigned long long m;
        m = __shfl_xor_sync(0xFFFFFFFFu, lmax, 1); lmax = (m > lmax) ? m : lmax;
        m = __shfl_xor_sync(0xFFFFFFFFu, lmax, 2); lmax = (m > lmax) ? m : lmax;
        if (l == 4) atomicMax(&g_amax[b], lmax);     // cg==1 lanes are l=4..7
    }
}

// ---------------- launcher ----------------
extern "C" void kernel_launch(void* const* d_in, const int* in_sizes, int n_in,
                              void* d_out, int out_size) {
    const float* x          = (const float*)d_in[0];   // [16,64,256,256]
    const float* score_init = (const float*)d_in[1];   // [16,65536]
    float* out = (float*)d_out;

    float* vecList = out;
    float* simList = out + (size_t)BB * NBVEC * CC;
    float* selPos  = simList + (size_t)BB * NBVEC * NPIX;

    zero_kernel<<<(BB * NPIX) / 256, 256>>>(selPos);
    argmax0_kernel<<<dim3(32, BB), 256>>>(score_init);
    between_kernel<<<BB, CC>>>(x, vecList, -1, 1);

    for (int it = 0; it < NBVEC; ++it) {
        // 18 blocks/batch * 16 batches = 288 blocks = one resident wave @2 CTA/SM
        main_kernel<<<dim3(18, BB), 256>>>(x, score_init, it == 0 ? 1 : 0,
                                           simList, it);
        int do_prep = (it + 1 < NBVEC) ? 1 : 0;
        between_kernel<<<BB, CC>>>(x, vecList, it, do_prep);
    }
}

// round 6
// speedup vs baseline: 1.0145x; 1.0145x over previous
#include <cuda_runtime.h>
#include <cstdint>

#define BB 16
#define CC 64
#define NPIX 65536          // 256*256
#define NBVEC 4
#define INV_TEMP (1.0f/20.0f)

// ---------------- device scratch (no allocations allowed) ----------------
__device__ float g_raw[BB][CC];
__device__ float g_vec[BB][CC];
__device__ float g_simsum[BB];
__device__ unsigned long long g_amax[BB];
__device__ float g_score[BB * NPIX];

// ---------------- helpers ----------------
__device__ __forceinline__ unsigned long long pack_score(float s, int n) {
    // score >= 0 -> float bits order-preserving; invert idx so ties pick lowest n.
    return ((unsigned long long)__float_as_uint(s) << 32) |
           (unsigned long long)(0xFFFFFFFFu - (unsigned)n);
}

// ---------------- kernel 1: zero selectedPos + reset amax ----------------
__global__ void zero_kernel(float* __restrict__ selPos) {
    int i = blockIdx.x * blockDim.x + threadIdx.x;
    selPos[i] = 0.0f;
    if (blockIdx.x == 0 && threadIdx.x < BB) g_amax[threadIdx.x] = 0ull;
}

// ---------------- kernel 2: argmax of score_init per batch ----------------
__global__ void argmax0_kernel(const float* __restrict__ score) {
    int b = blockIdx.y;
    const float* s = score + (size_t)b * NPIX;
    unsigned long long m = 0ull;
    for (int n = blockIdx.x * blockDim.x + threadIdx.x; n < NPIX;
         n += gridDim.x * blockDim.x) {
        unsigned long long p = pack_score(s[n], n);
        m = (p > m) ? p : m;
    }
    #pragma unroll
    for (int o = 16; o; o >>= 1) {
        unsigned long long t = __shfl_down_sync(0xFFFFFFFFu, m, o);
        m = (t > m) ? t : m;
    }
    __shared__ unsigned long long sm[8];
    int w = threadIdx.x >> 5;
    if ((threadIdx.x & 31) == 0) sm[w] = m;
    __syncthreads();
    if (threadIdx.x == 0) {
        unsigned long long mm = sm[0];
        for (int i = 1; i < (int)(blockDim.x >> 5); i++)
            mm = (sm[i] > mm) ? sm[i] : mm;
        atomicMax(&g_amax[b], mm);
    }
}

// -------- kernel 3: finish previous iter + prep next ----------------------
__global__ void between_kernel(const float* __restrict__ x,
                               float* __restrict__ vecList,
                               int finish_iter, int do_prep) {
    int b = blockIdx.x, c = threadIdx.x;   // 64 threads
    float fin = 0.0f;
    unsigned ind = 0;
    if (finish_iter >= 0)
        fin = g_vec[b][c] / g_simsum[b];
    if (do_prep)
        ind = 0xFFFFFFFFu - (unsigned)(g_amax[b] & 0xFFFFFFFFull);
    __syncthreads();
    if (finish_iter >= 0)
        vecList[((size_t)b * NBVEC + finish_iter) * CC + c] = fin;
    if (do_prep) {
        g_raw[b][c] = x[((size_t)(b * CC + c)) * NPIX + ind];
        g_vec[b][c] = 0.0f;
        if (c == 0) { g_simsum[b] = 0.0f; g_amax[b] = 0ull; }
    }
}

// ---------------- kernel 4: fused main pass ----------------
// Warp w (0..7) owns channels [w*8, w*8+8). Lane l owns pixels n0=tile*64+l*2
// (float2). All 8 warps cover the SAME 64 pixels per tile; d2 partials are
// exchanged through double-buffered smem with ONE barrier per tile.
// 4 CTAs/SM (64 regs target) -> 32 warps/SM for latency hiding.
__global__ void __launch_bounds__(256, 4)
main_kernel(const float* __restrict__ x,
            const float* __restrict__ score_init,
            int first_iter,
            float* __restrict__ simList,
            int iter) {
    const int b = blockIdx.y;
    const int t = threadIdx.x;
    const int w = t >> 5;           // channel-group / warp id, 0..7
    const int l = t & 31;           // lane -> pixel pair

    const float* xb   = x + (size_t)b * CC * NPIX + (size_t)w * 8 * NPIX;
    const float* scin = (first_iter ? score_init : (const float*)g_score) + (size_t)b * NPIX;
    float* scout = g_score + (size_t)b * NPIX;
    float* simo  = simList + ((size_t)b * NBVEC + iter) * NPIX;

    __shared__ float  sraw_sh[CC];
    __shared__ float2 sd2[2][8][32];
    if (t < CC) sraw_sh[t] = g_raw[b][t];
    __syncthreads();
    float sraw[8];
    #pragma unroll
    for (int i = 0; i < 8; i++) sraw[i] = sraw_sh[w * 8 + i];

    float acc[8];
    #pragma unroll
    for (int i = 0; i < 8; i++) acc[i] = 0.0f;
    float lsum = 0.0f;
    unsigned long long lmax = 0ull;

    int buf = 0;
    for (int tile = blockIdx.x; tile < NPIX / 64; tile += gridDim.x) {
        const int n0 = tile * 64 + l * 2;

        float2 v[8];
        #pragma unroll
        for (int i = 0; i < 8; i++)
            v[i] = __ldg((const float2*)(xb + (size_t)i * NPIX + n0));

        float2 d2 = make_float2(0.f, 0.f);
        #pragma unroll
        for (int i = 0; i < 8; i++) {
            float r = sraw[i], d;
            d = v[i].x - r; d2.x = fmaf(d, d, d2.x);
            d = v[i].y - r; d2.y = fmaf(d, d, d2.y);
        }
        sd2[buf][w][l] = d2;
        __syncthreads();      // the ONLY barrier per tile (double-buffered)
        {
            float2 p0 = sd2[buf][0][l], p1 = sd2[buf][1][l];
            float2 p2 = sd2[buf][2][l], p3 = sd2[buf][3][l];
            float2 p4 = sd2[buf][4][l], p5 = sd2[buf][5][l];
            float2 p6 = sd2[buf][6][l], p7 = sd2[buf][7][l];
            d2.x = ((p0.x + p1.x) + (p2.x + p3.x)) + ((p4.x + p5.x) + (p6.x + p7.x));
            d2.y = ((p0.y + p1.y) + (p2.y + p3.y)) + ((p4.y + p5.y) + (p6.y + p7.y));
        }
        buf ^= 1;

        float2 sim;
        sim.x = expf(-sqrtf(fmaxf(d2.x, 1e-12f)) * INV_TEMP);
        sim.y = expf(-sqrtf(fmaxf(d2.y, 1e-12f)) * INV_TEMP);

        #pragma unroll
        for (int i = 0; i < 8; i++) {
            acc[i] = fmaf(v[i].x, sim.x, acc[i]);
            acc[i] = fmaf(v[i].y, sim.y, acc[i]);
        }

        if (w == 0) {
            *(float2*)(simo + n0) = sim;
            lsum += sim.x + sim.y;
        } else if (w == 1) {
            float2 sc = __ldg((const float2*)(scin + n0));
            float2 ns;
            ns.x = (1.0f - sim.x) * sc.x;
            ns.y = (1.0f - sim.y) * sc.y;
            *(float2*)(scout + n0) = ns;
            unsigned long long p;
            p = pack_score(ns.x, n0 + 0); lmax = (p > lmax) ? p : lmax;
            p = pack_score(ns.y, n0 + 1); lmax = (p > lmax) ? p : lmax;
        }
    }

    // ---- final reductions (once per kernel) ----
    #pragma unroll
    for (int i = 0; i < 8; i++) {
        float a = acc[i];
        #pragma unroll
        for (int o = 16; o; o >>= 1)
            a += __shfl_down_sync(0xFFFFFFFFu, a, o);
        if (l == 0) atomicAdd(&g_vec[b][w * 8 + i], a);
    }
    if (w == 0) {
        #pragma unroll
        for (int o = 16; o; o >>= 1)
            lsum += __shfl_down_sync(0xFFFFFFFFu, lsum, o);
        if (l == 0) atomicAdd(&g_simsum[b], lsum);
    } else if (w == 1) {
        #pragma unroll
        for (int o = 16; o; o >>= 1) {
            unsigned long long m = __shfl_down_sync(0xFFFFFFFFu, lmax, o);
            lmax = (m > lmax) ? m : lmax;
        }
        if (l == 0) atomicMax(&g_amax[b], lmax);
    }
}

// ---------------- launcher ----------------
extern "C" void kernel_launch(void* const* d_in, const int* in_sizes, int n_in,
                              void* d_out, int out_size) {
    const float* x          = (const float*)d_in[0];   // [16,64,256,256]
    const float* score_init = (const float*)d_in[1];   // [16,65536]
    float* out = (float*)d_out;

    float* vecList = out;
    float* simList = out + (size_t)BB * NBVEC * CC;
    float* selPos  = simList + (size_t)BB * NBVEC * NPIX;

    zero_kernel<<<(BB * NPIX) / 256, 256>>>(selPos);
    argmax0_kernel<<<dim3(32, BB), 256>>>(score_init);
    between_kernel<<<BB, CC>>>(x, vecList, -1, 1);

    for (int it = 0; it < NBVEC; ++it) {
        // 37 blocks/batch * 16 batches = 592 = exactly 4 CTAs/SM, one wave
        main_kernel<<<dim3(37, BB), 256>>>(x, score_init, it == 0 ? 1 : 0,
                                           simList, it);
        int do_prep = (it + 1 < NBVEC) ? 1 : 0;
        between_kernel<<<BB, CC>>>(x, vecList, it, do_prep);
    }
}

// round 7
// speedup vs baseline: 1.1167x; 1.1007x over previous
#include <cuda_runtime.h>
#include <cstdint>

#define BB 16
#define CC 64
#define NPIX 65536          // 256*256
#define NBVEC 4
#define INV_TEMP (1.0f/20.0f)
#define TPX 128             // pixels per block-tile
#define NTILES (NPIX / TPX) // 512
#define GX 18               // blocks per batch (18*16 = 288 = 2/SM wave)
#define CHUNK ((NTILES + GX - 1) / GX)   // 29

// ---------------- device scratch (no allocations allowed) ----------------
__device__ float g_raw[BB][CC];
__device__ float g_vec[BB][CC];
__device__ float g_simsum[BB];
__device__ unsigned long long g_amax[BB];
__device__ float g_score[BB * NPIX];

// ---------------- helpers ----------------
__device__ __forceinline__ unsigned long long pack_score(float s, int n) {
    // score >= 0 -> float bits order-preserving; invert idx so ties pick lowest n.
    return ((unsigned long long)__float_as_uint(s) << 32) |
           (unsigned long long)(0xFFFFFFFFu - (unsigned)n);
}

// ---------------- kernel 1: zero selectedPos + reset amax ----------------
__global__ void zero_kernel(float* __restrict__ selPos) {
    int i = blockIdx.x * blockDim.x + threadIdx.x;
    selPos[i] = 0.0f;
    if (blockIdx.x == 0 && threadIdx.x < BB) g_amax[threadIdx.x] = 0ull;
}

// ---------------- kernel 2: argmax of score_init per batch ----------------
__global__ void argmax0_kernel(const float* __restrict__ score) {
    int b = blockIdx.y;
    const float* s = score + (size_t)b * NPIX;
    unsigned long long m = 0ull;
    for (int n = blockIdx.x * blockDim.x + threadIdx.x; n < NPIX;
         n += gridDim.x * blockDim.x) {
        unsigned long long p = pack_score(s[n], n);
        m = (p > m) ? p : m;
    }
    #pragma unroll
    for (int o = 16; o; o >>= 1) {
        unsigned long long t = __shfl_down_sync(0xFFFFFFFFu, m, o);
        m = (t > m) ? t : m;
    }
    __shared__ unsigned long long sm[8];
    int w = threadIdx.x >> 5;
    if ((threadIdx.x & 31) == 0) sm[w] = m;
    __syncthreads();
    if (threadIdx.x == 0) {
        unsigned long long mm = sm[0];
        for (int i = 1; i < (int)(blockDim.x >> 5); i++)
            mm = (sm[i] > mm) ? sm[i] : mm;
        atomicMax(&g_amax[b], mm);
    }
}

// -------- kernel 3: finish previous iter + prep next ----------------------
__global__ void between_kernel(const float* __restrict__ x,
                               float* __restrict__ vecList,
                               int finish_iter, int do_prep) {
    int b = blockIdx.x, c = threadIdx.x;   // 64 threads
    float fin = 0.0f;
    unsigned ind = 0;
    if (finish_iter >= 0)
        fin = g_vec[b][c] / g_simsum[b];
    if (do_prep)
        ind = 0xFFFFFFFFu - (unsigned)(g_amax[b] & 0xFFFFFFFFull);
    __syncthreads();
    if (finish_iter >= 0)
        vecList[((size_t)b * NBVEC + finish_iter) * CC + c] = fin;
    if (do_prep) {
        g_raw[b][c] = x[((size_t)(b * CC + c)) * NPIX + ind];
        g_vec[b][c] = 0.0f;
        if (c == 0) { g_simsum[b] = 0.0f; g_amax[b] = 0ull; }
    }
}

// ---------------- kernel 4: fused main pass, software-pipelined ----------
// Warp w (0..7) owns channels [w*8, w*8+8); lane l owns 4 px (float4).
// Tile = 128 px/block. Double register buffers: loads for tile t+1 are issued
// BEFORE computing tile t, so DRAM stays busy through the compute tail.
// d2 exchange: double-buffered smem, ONE barrier per tile.
#define LOAD_TILE(V, TILE)                                                   \
    {   const int n0_ = (TILE) * TPX + l * 4;                                \
        _Pragma("unroll")                                                    \
        for (int i = 0; i < 8; i++)                                          \
            V[i] = __ldg((const float4*)(xb + (size_t)i * NPIX + n0_));      \
    }

#define COMP_TILE(V, TILE)                                                   \
    {   const int n0_ = (TILE) * TPX + l * 4;                                \
        float4 d2 = make_float4(0.f, 0.f, 0.f, 0.f);                         \
        _Pragma("unroll")                                                    \
        for (int i = 0; i < 8; i++) {                                        \
            float r = sraw[i], d;                                            \
            d = V[i].x - r; d2.x = fmaf(d, d, d2.x);                         \
            d = V[i].y - r; d2.y = fmaf(d, d, d2.y);                         \
            d = V[i].z - r; d2.z = fmaf(d, d, d2.z);                         \
            d = V[i].w - r; d2.w = fmaf(d, d, d2.w);                         \
        }                                                                    \
        sd2[buf][w][l] = d2;                                                 \
        __syncthreads();                                                     \
        {                                                                    \
            float4 p0 = sd2[buf][0][l], p1 = sd2[buf][1][l];                 \
            float4 p2 = sd2[buf][2][l], p3 = sd2[buf][3][l];                 \
            float4 p4 = sd2[buf][4][l], p5 = sd2[buf][5][l];                 \
            float4 p6 = sd2[buf][6][l], p7 = sd2[buf][7][l];                 \
            d2.x = ((p0.x+p1.x)+(p2.x+p3.x)) + ((p4.x+p5.x)+(p6.x+p7.x));    \
            d2.y = ((p0.y+p1.y)+(p2.y+p3.y)) + ((p4.y+p5.y)+(p6.y+p7.y));    \
            d2.z = ((p0.z+p1.z)+(p2.z+p3.z)) + ((p4.z+p5.z)+(p6.z+p7.z));    \
            d2.w = ((p0.w+p1.w)+(p2.w+p3.w)) + ((p4.w+p5.w)+(p6.w+p7.w));    \
        }                                                                    \
        buf ^= 1;                                                            \
        float4 sim;                                                          \
        sim.x = expf(-sqrtf(fmaxf(d2.x, 1e-12f)) * INV_TEMP);                \
        sim.y = expf(-sqrtf(fmaxf(d2.y, 1e-12f)) * INV_TEMP);                \
        sim.z = expf(-sqrtf(fmaxf(d2.z, 1e-12f)) * INV_TEMP);                \
        sim.w = expf(-sqrtf(fmaxf(d2.w, 1e-12f)) * INV_TEMP);                \
        _Pragma("unroll")                                                    \
        for (int i = 0; i < 8; i++) {                                        \
            acc[i] = fmaf(V[i].x, sim.x, acc[i]);                            \
            acc[i] = fmaf(V[i].y, sim.y, acc[i]);                            \
            acc[i] = fmaf(V[i].z, sim.z, acc[i]);                            \
            acc[i] = fmaf(V[i].w, sim.w, acc[i]);                            \
        }                                                                    \
        if (w == 0) {                                                        \
            *(float4*)(simo + n0_) = sim;                                    \
            lsum += (sim.x + sim.y) + (sim.z + sim.w);                       \
        } else if (w == 1) {                                                 \
            float4 sc = __ldg((const float4*)(scin + n0_));                  \
            float4 ns;                                                       \
            ns.x = (1.0f - sim.x) * sc.x;  ns.y = (1.0f - sim.y) * sc.y;     \
            ns.z = (1.0f - sim.z) * sc.z;  ns.w = (1.0f - sim.w) * sc.w;     \
            *(float4*)(scout + n0_) = ns;                                    \
            unsigned long long p;                                            \
            p = pack_score(ns.x, n0_ + 0); lmax = (p > lmax) ? p : lmax;     \
            p = pack_score(ns.y, n0_ + 1); lmax = (p > lmax) ? p : lmax;     \
            p = pack_score(ns.z, n0_ + 2); lmax = (p > lmax) ? p : lmax;     \
            p = pack_score(ns.w, n0_ + 3); lmax = (p > lmax) ? p : lmax;     \
        }                                                                    \
    }

__global__ void __launch_bounds__(256, 2)
main_kernel(const float* __restrict__ x,
            const float* __restrict__ score_init,
            int first_iter,
            float* __restrict__ simList,
            int iter) {
    const int b = blockIdx.y;
    const int t = threadIdx.x;
    const int w = t >> 5;           // channel-group / warp id, 0..7
    const int l = t & 31;           // lane -> pixel quad

    const float* xb   = x + (size_t)b * CC * NPIX + (size_t)w * 8 * NPIX;
    const float* scin = (first_iter ? score_init : (const float*)g_score) + (size_t)b * NPIX;
    float* scout = g_score + (size_t)b * NPIX;
    float* simo  = simList + ((size_t)b * NBVEC + iter) * NPIX;

    __shared__ float  sraw_sh[CC];
    __shared__ float4 sd2[2][8][32];
    if (t < CC) sraw_sh[t] = g_raw[b][t];
    __syncthreads();
    float sraw[8];
    #pragma unroll
    for (int i = 0; i < 8; i++) sraw[i] = sraw_sh[w * 8 + i];

    float acc[8];
    #pragma unroll
    for (int i = 0; i < 8; i++) acc[i] = 0.0f;
    float lsum = 0.0f;
    unsigned long long lmax = 0ull;
    int buf = 0;

    // contiguous chunk of tiles for this block (uniform across warps)
    const int t0 = blockIdx.x * CHUNK;
    const int t1 = (t0 + CHUNK < NTILES) ? (t0 + CHUNK) : NTILES;

    float4 v0[8], v1[8];
    LOAD_TILE(v0, t0);
    int tile = t0;
    while (tile < t1) {
        if (tile + 1 < t1) LOAD_TILE(v1, tile + 1);
        COMP_TILE(v0, tile);
        tile++;
        if (tile >= t1) break;
        if (tile + 1 < t1) LOAD_TILE(v0, tile + 1);
        COMP_TILE(v1, tile);
        tile++;
    }

    // ---- final reductions (once per kernel) ----
    #pragma unroll
    for (int i = 0; i < 8; i++) {
        float a = acc[i];
        #pragma unroll
        for (int o = 16; o; o >>= 1)
            a += __shfl_down_sync(0xFFFFFFFFu, a, o);
        if (l == 0) atomicAdd(&g_vec[b][w * 8 + i], a);
    }
    if (w == 0) {
        #pragma unroll
        for (int o = 16; o; o >>= 1)
            lsum += __shfl_down_sync(0xFFFFFFFFu, lsum, o);
        if (l == 0) atomicAdd(&g_simsum[b], lsum);
    } else if (w == 1) {
        #pragma unroll
        for (int o = 16; o; o >>= 1) {
            unsigned long long m = __shfl_down_sync(0xFFFFFFFFu, lmax, o);
            lmax = (m > lmax) ? m : lmax;
        }
        if (l == 0) atomicMax(&g_amax[b], lmax);
    }
}

// ---------------- launcher ----------------
extern "C" void kernel_launch(void* const* d_in, const int* in_sizes, int n_in,
                              void* d_out, int out_size) {
    const float* x          = (const float*)d_in[0];   // [16,64,256,256]
    const float* score_init = (const float*)d_in[1];   // [16,65536]
    float* out = (float*)d_out;

    float* vecList = out;
    float* simList = out + (size_t)BB * NBVEC * CC;
    float* selPos  = simList + (size_t)BB * NBVEC * NPIX;

    zero_kernel<<<(BB * NPIX) / 256, 256>>>(selPos);
    argmax0_kernel<<<dim3(32, BB), 256>>>(score_init);
    between_kernel<<<BB, CC>>>(x, vecList, -1, 1);

    for (int it = 0; it < NBVEC; ++it) {
        main_kernel<<<dim3(GX, BB), 256>>>(x, score_init, it == 0 ? 1 : 0,
                                           simList, it);
        int do_prep = (it + 1 < NBVEC) ? 1 : 0;
        between_kernel<<<BB, CC>>>(x, vecList, it, do_prep);
    }
}